// round 3
// baseline (speedup 1.0000x reference)
#include <cuda_runtime.h>

// y[n,c,h,w] = a0*x[h] + a1*(x[h-1]+x[h+1]) + a2*(x[h-2]+x[h+2]) + a3*(x[h-3]+x[h+3])
// with reflect indexing along H (reflect(i) = -i if i<0, 2H-2-i if i>=H).
// x: (N, C, H, W) fp32, alpha: (C, 4) fp32.

#define HH 256
#define WW 256
#define W4 (WW / 4)           // 64 float4 per row
#define PLANES_PER_BLOCK 4    // 4 * 64 = 256 threads

__global__ __launch_bounds__(256, 1)
void hartley_conv_kernel(const float4* __restrict__ x,
                         const float*  __restrict__ alpha,
                         float4* __restrict__ y,
                         int planes, int C)
{
    const int plane = blockIdx.x * PLANES_PER_BLOCK + (threadIdx.x >> 6);
    const int lane  = threadIdx.x & 63;
    if (plane >= planes) return;

    const int c = plane % C;
    const float a0 = alpha[c * 4 + 0];
    const float a1 = alpha[c * 4 + 1];
    const float a2 = alpha[c * 4 + 2];
    const float a3 = alpha[c * 4 + 3];

    const float4* __restrict__ xp = x + (size_t)plane * (HH * W4) + lane;
    float4*       __restrict__ yp = y + (size_t)plane * (HH * W4) + lane;

    // Sliding window: r[j] = x[reflect(h - 3 + j)], j = 0..6.
    // At h = 0: rows are reflect(-3..3) = 3,2,1,0,1,2,3.
    float4 r0, r1, r2, r3, r4, r5, r6;
    r3 = xp[0 * W4];
    r2 = xp[1 * W4]; r4 = r2;
    r1 = xp[2 * W4]; r5 = r1;
    r0 = xp[3 * W4]; r6 = r0;

    #pragma unroll 4
    for (int h = 0; h < HH; ++h) {
        float4 out;
        out.x = fmaf(a3, r0.x + r6.x, fmaf(a2, r1.x + r5.x, fmaf(a1, r2.x + r4.x, a0 * r3.x)));
        out.y = fmaf(a3, r0.y + r6.y, fmaf(a2, r1.y + r5.y, fmaf(a1, r2.y + r4.y, a0 * r3.y)));
        out.z = fmaf(a3, r0.z + r6.z, fmaf(a2, r1.z + r5.z, fmaf(a1, r2.z + r4.z, a0 * r3.z)));
        out.w = fmaf(a3, r0.w + r6.w, fmaf(a2, r1.w + r5.w, fmaf(a1, r2.w + r4.w, a0 * r3.w)));
        yp[h * W4] = out;

        // advance window: new r6 = x[reflect(h + 4)]
        r0 = r1; r1 = r2; r2 = r3; r3 = r4; r4 = r5; r5 = r6;
        int nh = h + 4;
        if (nh >= HH) nh = 2 * HH - 2 - nh;   // reflect (only last 3 iters)
        r6 = xp[nh * W4];
    }
}

extern "C" void kernel_launch(void* const* d_in, const int* in_sizes, int n_in,
                              void* d_out, int out_size)
{
    const float4* x     = (const float4*)d_in[0];
    const float*  alpha = (const float*)d_in[1];
    float4*       y     = (float4*)d_out;

    const int C      = in_sizes[1] / 4;          // alpha is (C, 1+M) = (C, 4)
    const int planes = in_sizes[0] / (HH * WW);  // N * C

    const int grid = (planes + PLANES_PER_BLOCK - 1) / PLANES_PER_BLOCK;
    hartley_conv_kernel<<<grid, 256>>>(x, alpha, y, planes, C);
}